// round 1
// baseline (speedup 1.0000x reference)
#include <cuda_runtime.h>
#include <math.h>

#define BSZ 4

// ---------------- scratch (device globals; no allocations allowed) ----------
__device__ float g_v  [16777216];   // [4,64,256,256]
__device__ float g_x1 [16777216];   // [4,64,256,256]
__device__ float g_x1d[ 4194304];   // [4,64,128,128]
__device__ float g_x2 [ 6291456];   // [4,96,128,128]
__device__ float g_x2d[ 1572864];   // [4,96,64,64]
__device__ float g_xb [ 2097152];   // [4,128,64,64]
__device__ float g_x2c[14680064];   // [4,224,128,128]
__device__ float g_x2o[ 6291456];   // [4,96,128,128]
__device__ float g_x1c[41943040];   // [4,160,256,256]
__device__ float g_x1o[16777216];   // [4,64,256,256]

__device__ float g_XW [ 3932160];   // max [4,160,256,12] complex
__device__ float g_XF [  368640];   // max [4,160,24,12] complex
__device__ float g_OF [  368640];   // max [4,Co,2m1,m2] complex
__device__ float g_Z  [ 1572864];   // max [4,64,256,12] complex
__device__ float g_tw [   26112];   // twiddle tables (complex interleaved)

// twiddle table complex offsets
#define TW0 0
#define TH0 3072
#define TW1 9216
#define TH1 10240
#define TW2 12288
#define TH2 12544

__device__ __forceinline__ float gelu_f(float x) {
    return 0.5f * x * (1.0f + erff(x * 0.70710678118654752f));
}

// ---------------- twiddle init -----------------------------------------------
__global__ void k_init_tw() {
    const int cfg[3][5] = {{256,12,12,TW0,TH0},{128,8,8,TW1,TH1},{64,4,4,TW2,TH2}};
    int tid = blockIdx.x * blockDim.x + threadIdx.x;
    int nth = gridDim.x * blockDim.x;
    for (int c = 0; c < 3; c++) {
        int H = cfg[c][0], m1 = cfg[c][1], m2 = cfg[c][2];
        int offW = cfg[c][3], offH = cfg[c][4];
        int nW = H * m2;
        for (int e = tid; e < nW; e += nth) {
            int w = e / m2, kw = e % m2;
            int p = (w * kw) % H;
            double s, co; sincos(2.0 * 3.14159265358979323846 * (double)p / (double)H, &s, &co);
            g_tw[(offW + e) * 2]     = (float)co;
            g_tw[(offW + e) * 2 + 1] = (float)(-s);
        }
        int m1t2 = 2 * m1;
        int nH = H * m1t2;
        for (int e = tid; e < nH; e += nth) {
            int h = e / m1t2, j = e % m1t2;
            int kh = (j < m1) ? j : (H - 2 * m1 + j);
            int p = (kh * h) % H;
            double s, co; sincos(2.0 * 3.14159265358979323846 * (double)p / (double)H, &s, &co);
            g_tw[(offH + e) * 2]     = (float)co;
            g_tw[(offH + e) * 2 + 1] = (float)(-s);
        }
    }
}

// ---------------- lift: x[B,H,W,6] -> v[B,64,H,W] ----------------------------
__global__ void k_lift(const float* __restrict__ x, const float* __restrict__ w,
                       const float* __restrict__ b) {
    const int HW = 256 * 256;
    int idx = blockIdx.x * blockDim.x + threadIdx.x;
    if (idx >= BSZ * 64 * HW) return;
    int p  = idx % HW;
    int c  = (idx / HW) % 64;
    int bb = idx / (HW * 64);
    const float* xp = x + ((size_t)bb * HW + p) * 6;
    float acc = b[c];
    #pragma unroll
    for (int i = 0; i < 6; i++) acc += xp[i] * w[c * 6 + i];
    g_v[idx] = acc;
}

// ---------------- partial DFT along W: x[BC,H,W] -> XW[BC,H,m2] cplx ---------
__global__ void k_fwd_w(const float* __restrict__ xin, int total, int H, int W, int m2,
                        const float* __restrict__ tw) {
    int idx = blockIdx.x * blockDim.x + threadIdx.x;
    if (idx >= total) return;
    int kw = idx % m2;
    int h  = (idx / m2) % H;
    int bc = idx / (m2 * H);
    const float* row = xin + ((size_t)bc * H + h) * W;
    float ar = 0.f, ai = 0.f;
    for (int w = 0; w < W; w++) {
        float xv = row[w];
        float tr = tw[(w * m2 + kw) * 2];
        float ti = tw[(w * m2 + kw) * 2 + 1];
        ar += xv * tr;
        ai += xv * ti;
    }
    g_XW[idx * 2]     = ar;
    g_XW[idx * 2 + 1] = ai;
}

// ---------------- partial DFT along H: XW -> XF[BC,2m1,m2] cplx --------------
__global__ void k_fwd_h(int total, int H, int m1, int m2, const float* __restrict__ tw) {
    int idx = blockIdx.x * blockDim.x + threadIdx.x;
    if (idx >= total) return;
    int m1t2 = 2 * m1;
    int kw = idx % m2;
    int kk = (idx / m2) % m1t2;
    int bc = idx / (m2 * m1t2);
    float ar = 0.f, ai = 0.f;
    for (int h = 0; h < H; h++) {
        float xr = g_XW[(((size_t)bc * H + h) * m2 + kw) * 2];
        float xi = g_XW[(((size_t)bc * H + h) * m2 + kw) * 2 + 1];
        float tr = tw[(h * m1t2 + kk) * 2];
        float ti = tw[(h * m1t2 + kk) * 2 + 1];
        ar += xr * tr - xi * ti;
        ai += xr * ti + xi * tr;
    }
    g_XF[idx * 2]     = ar;
    g_XF[idx * 2 + 1] = ai;
}

// ---------------- per-mode channel mix: XF -> OF[B,Co,2m1,m2] cplx -----------
__global__ void k_mix(int total, int Ci, int Co, int m1, int m2,
                      const float* __restrict__ w1, const float* __restrict__ w2) {
    int idx = blockIdx.x * blockDim.x + threadIdx.x;
    if (idx >= total) return;
    int m1t2 = 2 * m1;
    int kw = idx % m2;
    int kk = (idx / m2) % m1t2;
    int o  = (idx / (m2 * m1t2)) % Co;
    int b  = idx / (m2 * m1t2 * Co);
    int kkr = (kk < m1) ? kk : kk - m1;
    const float* wsel = (kk < m1) ? w1 : w2;
    float orr = 0.f, oii = 0.f;
    for (int i = 0; i < Ci; i++) {
        size_t xo = (((size_t)(b * Ci + i) * m1t2 + kk) * m2 + kw) * 2;
        float xr = g_XF[xo], xi = g_XF[xo + 1];
        const float* wp = wsel + (((size_t)(i * Co + o) * m1 + kkr) * m2 + kw) * 2;
        float wr = wp[0], wi = wp[1];
        orr += xr * wr - xi * wi;
        oii += xr * wi + xi * wr;
    }
    g_OF[idx * 2]     = orr;
    g_OF[idx * 2 + 1] = oii;
}

// ---------------- inverse DFT along H: OF -> Z[B,Co,H,m2] cplx ---------------
__global__ void k_inv_h(int total, int H, int m1, int m2, const float* __restrict__ tw) {
    int idx = blockIdx.x * blockDim.x + threadIdx.x;
    if (idx >= total) return;
    int m1t2 = 2 * m1;
    int kw = idx % m2;
    int h  = (idx / m2) % H;
    int bo = idx / (m2 * H);
    float zr = 0.f, zi = 0.f;
    for (int kk = 0; kk < m1t2; kk++) {
        size_t oo = (((size_t)bo * m1t2 + kk) * m2 + kw) * 2;
        float fr = g_OF[oo], fi = g_OF[oo + 1];
        float tr = tw[(h * m1t2 + kk) * 2];
        float ti = tw[(h * m1t2 + kk) * 2 + 1];
        // multiply by conj(forward twiddle) = e^{+i theta}
        zr += fr * tr + fi * ti;
        zi += fi * tr - fr * ti;
    }
    g_Z[idx * 2]     = zr;
    g_Z[idx * 2 + 1] = zi;
}

// -------- fuse: out = gelu( invW(Z)/HW + conv1x1(xin) + bias ) ---------------
__global__ void k_fuse(const float* __restrict__ xin, int total, int Ci, int Co,
                       int H, int W, int m2, const float* __restrict__ tw,
                       const float* __restrict__ cw, const float* __restrict__ cb,
                       float invHW, float* __restrict__ out) {
    int idx = blockIdx.x * blockDim.x + threadIdx.x;
    if (idx >= total) return;
    int w = idx % W;
    int h = (idx / W) % H;
    int o = (idx / (W * H)) % Co;
    int b = idx / (W * H * Co);
    const int HW = H * W;

    // inverse DFT along W (real output, Hermitian weights)
    size_t zbase = (((size_t)(b * Co + o) * H + h) * m2) * 2;
    float spec = 0.f;
    for (int kw = 0; kw < m2; kw++) {
        float zr = g_Z[zbase + kw * 2];
        float zi = g_Z[zbase + kw * 2 + 1];
        float tr = tw[(w * m2 + kw) * 2];
        float ti = tw[(w * m2 + kw) * 2 + 1];
        float v = zr * tr + zi * ti;   // Re(z * conj(tw))
        spec += (kw == 0) ? v : 2.0f * v;
    }

    // conv1x1
    float acc = cb[o];
    const float* xp = xin + (size_t)b * Ci * HW + (size_t)h * W + w;
    const float* wr = cw + (size_t)o * Ci;
    for (int i = 0; i < Ci; i += 4) {
        float4 wv = *(const float4*)(wr + i);
        acc += xp[0] * wv.x;
        acc += xp[(size_t)HW] * wv.y;
        acc += xp[2 * (size_t)HW] * wv.z;
        acc += xp[3 * (size_t)HW] * wv.w;
        xp += 4 * (size_t)HW;
    }
    out[idx] = gelu_f(spec * invHW + acc);
}

// ---------------- 2x2 mean pool ----------------------------------------------
__global__ void k_pool(const float* __restrict__ in, int total, int H, int W,
                       float* __restrict__ out) {
    int idx = blockIdx.x * blockDim.x + threadIdx.x;
    if (idx >= total) return;
    int Ho = H / 2, Wo = W / 2;
    int wo = idx % Wo;
    int ho = (idx / Wo) % Ho;
    int bc = idx / (Wo * Ho);
    const float* p = in + ((size_t)bc * H + 2 * ho) * W + 2 * wo;
    out[idx] = 0.25f * (p[0] + p[1] + p[W] + p[W + 1]);
}

// ---------------- bilinear 2x upsample (half-pixel) into concat dst ----------
__global__ void k_up(const float* __restrict__ in, int total, int C, int H, int W,
                     float* __restrict__ dst, int Ct, int coff) {
    int idx = blockIdx.x * blockDim.x + threadIdx.x;
    if (idx >= total) return;
    int Ho = 2 * H, Wo = 2 * W;
    int wo = idx % Wo;
    int ho = (idx / Wo) % Ho;
    int c  = (idx / (Wo * Ho)) % C;
    int b  = idx / (Wo * Ho * C);

    int kh = ho >> 1, ha, hb; float wha, whb;
    if (ho & 1) { ha = kh; hb = (kh + 1 < H) ? kh + 1 : H - 1; wha = 0.75f; whb = 0.25f; }
    else        { ha = (kh - 1 >= 0) ? kh - 1 : 0; hb = kh;    wha = 0.25f; whb = 0.75f; }
    int kw = wo >> 1, wa, wb; float wwa, wwb;
    if (wo & 1) { wa = kw; wb = (kw + 1 < W) ? kw + 1 : W - 1; wwa = 0.75f; wwb = 0.25f; }
    else        { wa = (kw - 1 >= 0) ? kw - 1 : 0; wb = kw;    wwa = 0.25f; wwb = 0.75f; }

    const float* base = in + (size_t)(b * C + c) * H * W;
    float v = wha * (wwa * base[(size_t)ha * W + wa] + wwb * base[(size_t)ha * W + wb])
            + whb * (wwa * base[(size_t)hb * W + wa] + wwb * base[(size_t)hb * W + wb]);
    dst[((size_t)(b * Ct + coff + c) * Ho + ho) * Wo + wo] = v;
}

// ---------------- channel-block copy for concat ------------------------------
__global__ void k_copych(const float* __restrict__ in, int total, int C, int HW,
                         float* __restrict__ dst, int Ct, int coff) {
    int idx = blockIdx.x * blockDim.x + threadIdx.x;
    if (idx >= total) return;
    int p = idx % HW;
    int c = (idx / HW) % C;
    int b = idx / (HW * C);
    dst[((size_t)(b * Ct + coff + c)) * HW + p] = in[idx];
}

// ---------------- head: fc1(64->256) + gelu + fc2(256->3), per pixel ---------
__global__ void k_head(const float* __restrict__ xin, const float* __restrict__ w1,
                       const float* __restrict__ b1, const float* __restrict__ w2,
                       const float* __restrict__ b2, float* __restrict__ out) {
    const int HW = 256 * 256;
    int idx = blockIdx.x * blockDim.x + threadIdx.x;
    if (idx >= BSZ * HW) return;
    int p = idx % HW;
    int b = idx / HW;

    float inr[64];
    const float* xp = xin + (size_t)b * 64 * HW + p;
    #pragma unroll
    for (int i = 0; i < 64; i++) inr[i] = xp[(size_t)i * HW];

    float o0 = b2[0], o1 = b2[1], o2 = b2[2];
    for (int o = 0; o < 256; o++) {
        float acc = b1[o];
        const float4* wrow = (const float4*)(w1 + o * 64);
        #pragma unroll
        for (int i = 0; i < 16; i++) {
            float4 wv = wrow[i];
            acc += inr[4*i] * wv.x + inr[4*i+1] * wv.y + inr[4*i+2] * wv.z + inr[4*i+3] * wv.w;
        }
        float hh = gelu_f(acc);
        o0 += hh * w2[o];
        o1 += hh * w2[256 + o];
        o2 += hh * w2[512 + o];
    }
    float* op = out + (size_t)idx * 3;
    op[0] = o0; op[1] = o1; op[2] = o2;
}

// =============================================================================
static inline int grid_of(int total) { return (total + 255) / 256; }

static void spectral_block(const float* xin, int Ci, int Co, int H, int m1,
                           const float* w1, const float* w2,
                           const float* cw, const float* cb,
                           const float* twW, const float* twH, float* out) {
    const int W = H, m2 = m1, m1t2 = 2 * m1;
    int t;
    t = BSZ * Ci * H * m2;
    k_fwd_w<<<grid_of(t), 256>>>(xin, t, H, W, m2, twW);
    t = BSZ * Ci * m1t2 * m2;
    k_fwd_h<<<grid_of(t), 256>>>(t, H, m1, m2, twH);
    t = BSZ * Co * m1t2 * m2;
    k_mix<<<grid_of(t), 256>>>(t, Ci, Co, m1, m2, w1, w2);
    t = BSZ * Co * H * m2;
    k_inv_h<<<grid_of(t), 256>>>(t, H, m1, m2, twH);
    t = BSZ * Co * H * W;
    k_fuse<<<grid_of(t), 256>>>(xin, t, Ci, Co, H, W, m2, twW, cw, cb,
                                1.0f / (float)(H * W), out);
}

extern "C" void kernel_launch(void* const* d_in, const int* in_sizes, int n_in,
                              void* d_out, int out_size) {
    const float* x      = (const float*)d_in[0];
    const float* fcin_w = (const float*)d_in[1];
    const float* fcin_b = (const float*)d_in[2];
    const float* sc1_w1 = (const float*)d_in[3];
    const float* sc1_w2 = (const float*)d_in[4];
    const float* c1_w   = (const float*)d_in[5];
    const float* c1_b   = (const float*)d_in[6];
    const float* sc2_w1 = (const float*)d_in[7];
    const float* sc2_w2 = (const float*)d_in[8];
    const float* c2_w   = (const float*)d_in[9];
    const float* c2_b   = (const float*)d_in[10];
    const float* scb_w1 = (const float*)d_in[11];
    const float* scb_w2 = (const float*)d_in[12];
    const float* cb_w   = (const float*)d_in[13];
    const float* cb_b   = (const float*)d_in[14];
    const float* su2_w1 = (const float*)d_in[15];
    const float* su2_w2 = (const float*)d_in[16];
    const float* u2_w   = (const float*)d_in[17];
    const float* u2_b   = (const float*)d_in[18];
    const float* su1_w1 = (const float*)d_in[19];
    const float* su1_w2 = (const float*)d_in[20];
    const float* u1_w   = (const float*)d_in[21];
    const float* u1_b   = (const float*)d_in[22];
    const float* fc1_w  = (const float*)d_in[23];
    const float* fc1_b  = (const float*)d_in[24];
    const float* fc2_w  = (const float*)d_in[25];
    const float* fc2_b  = (const float*)d_in[26];

    float *p_v, *p_x1, *p_x1d, *p_x2, *p_x2d, *p_xb, *p_x2c, *p_x2o, *p_x1c, *p_x1o, *p_tw;
    cudaGetSymbolAddress((void**)&p_v,   g_v);
    cudaGetSymbolAddress((void**)&p_x1,  g_x1);
    cudaGetSymbolAddress((void**)&p_x1d, g_x1d);
    cudaGetSymbolAddress((void**)&p_x2,  g_x2);
    cudaGetSymbolAddress((void**)&p_x2d, g_x2d);
    cudaGetSymbolAddress((void**)&p_xb,  g_xb);
    cudaGetSymbolAddress((void**)&p_x2c, g_x2c);
    cudaGetSymbolAddress((void**)&p_x2o, g_x2o);
    cudaGetSymbolAddress((void**)&p_x1c, g_x1c);
    cudaGetSymbolAddress((void**)&p_x1o, g_x1o);
    cudaGetSymbolAddress((void**)&p_tw,  g_tw);

    const float* tw_W0 = p_tw + 2 * TW0;
    const float* tw_H0 = p_tw + 2 * TH0;
    const float* tw_W1 = p_tw + 2 * TW1;
    const float* tw_H1 = p_tw + 2 * TH1;
    const float* tw_W2 = p_tw + 2 * TW2;
    const float* tw_H2 = p_tw + 2 * TH2;

    k_init_tw<<<32, 256>>>();

    // lift 6 -> 64
    {
        int t = BSZ * 64 * 256 * 256;
        k_lift<<<grid_of(t), 256>>>(x, fcin_w, fcin_b);
    }

    // encoder level 1: 64 -> 64 @ 256
    spectral_block(p_v, 64, 64, 256, 12, sc1_w1, sc1_w2, c1_w, c1_b, tw_W0, tw_H0, p_x1);
    {
        int t = BSZ * 64 * 128 * 128;
        k_pool<<<grid_of(t), 256>>>(p_x1, t, 256, 256, p_x1d);
    }

    // encoder level 2: 64 -> 96 @ 128
    spectral_block(p_x1d, 64, 96, 128, 8, sc2_w1, sc2_w2, c2_w, c2_b, tw_W1, tw_H1, p_x2);
    {
        int t = BSZ * 96 * 64 * 64;
        k_pool<<<grid_of(t), 256>>>(p_x2, t, 128, 128, p_x2d);
    }

    // bottleneck: 96 -> 128 @ 64
    spectral_block(p_x2d, 96, 128, 64, 4, scb_w1, scb_w2, cb_w, cb_b, tw_W2, tw_H2, p_xb);

    // x2c = concat(up(xb), x2) -> [4,224,128,128]
    {
        int t = BSZ * 128 * 128 * 128;
        k_up<<<grid_of(t), 256>>>(p_xb, t, 128, 64, 64, p_x2c, 224, 0);
        t = BSZ * 96 * 128 * 128;
        k_copych<<<grid_of(t), 256>>>(p_x2, t, 96, 128 * 128, p_x2c, 224, 128);
    }

    // decoder level 2: 224 -> 96 @ 128
    spectral_block(p_x2c, 224, 96, 128, 8, su2_w1, su2_w2, u2_w, u2_b, tw_W1, tw_H1, p_x2o);

    // x1c = concat(up(x2o), x1) -> [4,160,256,256]
    {
        int t = BSZ * 96 * 256 * 256;
        k_up<<<grid_of(t), 256>>>(p_x2o, t, 96, 128, 128, p_x1c, 160, 0);
        t = BSZ * 64 * 256 * 256;
        k_copych<<<grid_of(t), 256>>>(p_x1, t, 64, 256 * 256, p_x1c, 160, 96);
    }

    // decoder level 1: 160 -> 64 @ 256
    spectral_block(p_x1c, 160, 64, 256, 12, su1_w1, su1_w2, u1_w, u1_b, tw_W0, tw_H0, p_x1o);

    // head: fc1 + gelu + fc2 fused
    {
        int t = BSZ * 256 * 256;
        k_head<<<grid_of(t), 256>>>(p_x1o, fc1_w, fc1_b, fc2_w, fc2_b, (float*)d_out);
    }
}

// round 2
// speedup vs baseline: 1.4859x; 1.4859x over previous
#include <cuda_runtime.h>
#include <math.h>

#define BSZ 4

// ---------------- scratch (device globals; no allocations allowed) ----------
__device__ float g_v  [16777216];   // [4,64,256,256]
__device__ float g_x1 [16777216];   // [4,64,256,256]
__device__ float g_x1d[ 4194304];   // [4,64,128,128]
__device__ float g_x2 [ 6291456];   // [4,96,128,128]
__device__ float g_x2d[ 1572864];   // [4,96,64,64]
__device__ float g_xb [ 2097152];   // [4,128,64,64]
__device__ float g_x2c[14680064];   // [4,224,128,128]
__device__ float g_x2o[ 6291456];   // [4,96,128,128]
__device__ float g_x1c[41943040];   // [4,160,256,256]
__device__ float g_x1o[16777216];   // [4,64,256,256]

__device__ float g_XW [ 3932160];   // max [4,160,256,12] complex
__device__ float g_XF [  368640];   // max [4,160,24,12] complex
__device__ float g_OF [  368640];   // max [4,Co,2m1,m2] complex
__device__ float g_Z  [ 1572864];   // max [4,64,256,12] complex (scaled)
__device__ float g_tw [   26112];   // twiddle tables (complex interleaved)

#define TW0 0
#define TH0 3072
#define TW1 9216
#define TH1 10240
#define TW2 12288
#define TH2 12544

__device__ __forceinline__ float gelu_f(float x) {
    return 0.5f * x * (1.0f + erff(x * 0.70710678118654752f));
}

// ---------------- twiddle init -----------------------------------------------
__global__ void k_init_tw() {
    const int cfg[3][5] = {{256,12,12,TW0,TH0},{128,8,8,TW1,TH1},{64,4,4,TW2,TH2}};
    int tid = blockIdx.x * blockDim.x + threadIdx.x;
    int nth = gridDim.x * blockDim.x;
    for (int c = 0; c < 3; c++) {
        int H = cfg[c][0], m1 = cfg[c][1], m2 = cfg[c][2];
        int offW = cfg[c][3], offH = cfg[c][4];
        int nW = H * m2;
        for (int e = tid; e < nW; e += nth) {
            int w = e / m2, kw = e % m2;
            int p = (w * kw) % H;
            double s, co; sincos(2.0 * 3.14159265358979323846 * (double)p / (double)H, &s, &co);
            g_tw[(offW + e) * 2]     = (float)co;
            g_tw[(offW + e) * 2 + 1] = (float)(-s);
        }
        int m1t2 = 2 * m1;
        int nH = H * m1t2;
        for (int e = tid; e < nH; e += nth) {
            int h = e / m1t2, j = e % m1t2;
            int kh = (j < m1) ? j : (H - 2 * m1 + j);
            int p = (kh * h) % H;
            double s, co; sincos(2.0 * 3.14159265358979323846 * (double)p / (double)H, &s, &co);
            g_tw[(offH + e) * 2]     = (float)co;
            g_tw[(offH + e) * 2 + 1] = (float)(-s);
        }
    }
}

// ---------------- lift: x[B,H,W,6] -> v[B,64,H,W] ----------------------------
__global__ void k_lift(const float* __restrict__ x, const float* __restrict__ w,
                       const float* __restrict__ b) {
    const int HW = 256 * 256;
    int idx = blockIdx.x * blockDim.x + threadIdx.x;
    if (idx >= BSZ * 64 * HW) return;
    int p  = idx % HW;
    int c  = (idx / HW) % 64;
    int bb = idx / (HW * 64);
    const float* xp = x + ((size_t)bb * HW + p) * 6;
    float acc = b[c];
    #pragma unroll
    for (int i = 0; i < 6; i++) acc += xp[i] * w[c * 6 + i];
    g_v[idx] = acc;
}

// ------- fwd DFT along W as tiled GEMM: out[r,kc] = sum_w x[r,w]*T[w,kc] -----
// rows r = BSZ*Ci*H, kc = 0..2*m2-1 (interleaved re/im). 32 rows per block.
__global__ void k_fwd_w(const float* __restrict__ xin, int R, int W, int m2,
                        const float* __restrict__ tw) {
    __shared__ float xs[32][65];
    __shared__ float tws[64][24];
    int m2c = 2 * m2;
    int r0 = blockIdx.x * 32;
    int tid = threadIdx.x;
    int row_l = tid & 31;
    int kc0 = tid >> 5;                 // 0..7
    float acc0 = 0.f, acc1 = 0.f, acc2 = 0.f;

    for (int k0 = 0; k0 < W; k0 += 64) {
        for (int l = tid; l < 32 * 64; l += 256) {
            int r = l >> 6, k = l & 63;
            xs[r][k] = xin[(size_t)(r0 + r) * W + k0 + k];
        }
        for (int l = tid; l < 64 * m2c; l += 256) {
            int k = l / m2c, kc = l % m2c;
            tws[k][kc] = tw[(size_t)(k0 + k) * m2c + kc];
        }
        __syncthreads();
        #pragma unroll 8
        for (int k = 0; k < 64; k++) {
            float xv = xs[row_l][k];
            acc0 += xv * tws[k][kc0];
            if (kc0 + 8 < m2c)  acc1 += xv * tws[k][kc0 + 8];
            if (kc0 + 16 < m2c) acc2 += xv * tws[k][kc0 + 16];
        }
        __syncthreads();
    }
    size_t base = (size_t)(r0 + row_l) * m2c;
    g_XW[base + kc0] = acc0;
    if (kc0 + 8 < m2c)  g_XW[base + kc0 + 8]  = acc1;
    if (kc0 + 16 < m2c) g_XW[base + kc0 + 16] = acc2;
}

// ------- fwd DFT along H: per-bc block. XW[bc,H,m2]c -> XF[bc,2m1,m2]c -------
__global__ void k_fwd_h(int H, int m1, int m2, const float* __restrict__ tw) {
    __shared__ float xw_s[256 * 24];        // H * 2*m2 floats (max 6144)
    int bc = blockIdx.x;
    int tid = threadIdx.x;
    int m1t2 = 2 * m1, m2c = 2 * m2;
    int nload = H * m2c;
    const float* src = g_XW + (size_t)bc * nload;
    for (int l = tid; l < nload; l += 256) xw_s[l] = src[l];
    __syncthreads();

    int nout = m1t2 * m2;
    for (int e = tid; e < nout; e += 256) {
        int kw = e % m2;
        int kk = e / m2;
        float ar = 0.f, ai = 0.f;
        for (int h = 0; h < H; h++) {
            float xr = xw_s[h * m2c + 2 * kw];
            float xi = xw_s[h * m2c + 2 * kw + 1];
            float tr = tw[(h * m1t2 + kk) * 2];
            float ti = tw[(h * m1t2 + kk) * 2 + 1];
            ar += xr * tr - xi * ti;
            ai += xr * ti + xi * tr;
        }
        size_t oo = ((size_t)bc * m1t2 * m2 + e) * 2;
        g_XF[oo] = ar;
        g_XF[oo + 1] = ai;
    }
}

// ------- per-mode channel mix: block = (b, kk). XF -> OF ---------------------
__global__ void k_mix(int Ci, int Co, int m1, int m2,
                      const float* __restrict__ w1, const float* __restrict__ w2) {
    __shared__ float xf_s[160 * 24];        // Ci * 2*m2 (max 3840)
    int m1t2 = 2 * m1, m2c = 2 * m2;
    int kk = blockIdx.x % m1t2;
    int b  = blockIdx.x / m1t2;
    int tid = threadIdx.x;

    for (int l = tid; l < Ci * m2c; l += 256) {
        int i = l / m2c, kc = l % m2c;
        xf_s[l] = g_XF[(((size_t)(b * Ci + i) * m1t2 + kk) * m2) * 2 + kc];
    }
    __syncthreads();

    int kkr = (kk < m1) ? kk : kk - m1;
    const float* wsel = (kk < m1) ? w1 : w2;
    int nout = Co * m2;
    for (int e = tid; e < nout; e += 256) {
        int kw = e % m2;
        int o  = e / m2;
        float orr = 0.f, oii = 0.f;
        for (int i = 0; i < Ci; i++) {
            float xr = xf_s[i * m2c + 2 * kw];
            float xi = xf_s[i * m2c + 2 * kw + 1];
            const float* wp = wsel + (((size_t)(i * Co + o) * m1 + kkr) * m2 + kw) * 2;
            float wr = wp[0], wi = wp[1];
            orr += xr * wr - xi * wi;
            oii += xr * wi + xi * wr;
        }
        size_t oo = (((size_t)(b * Co + o) * m1t2 + kk) * m2 + kw) * 2;
        g_OF[oo] = orr;
        g_OF[oo + 1] = oii;
    }
}

// ------- inverse DFT along H: per-bo block; scales by invHW ------------------
__global__ void k_inv_h(int H, int m1, int m2, const float* __restrict__ tw,
                        float invHW) {
    __shared__ float of_s[1152];            // 2*m1*m2*2 (max 576 cplx)
    int bo = blockIdx.x;
    int tid = threadIdx.x;
    int m1t2 = 2 * m1;
    int nload = m1t2 * m2 * 2;
    const float* src = g_OF + (size_t)bo * nload;
    for (int l = tid; l < nload; l += 256) of_s[l] = src[l];
    __syncthreads();

    int nout = H * m2;
    for (int e = tid; e < nout; e += 256) {
        int kw = e % m2;
        int h  = e / m2;
        float zr = 0.f, zi = 0.f;
        for (int kk = 0; kk < m1t2; kk++) {
            float fr = of_s[(kk * m2 + kw) * 2];
            float fi = of_s[(kk * m2 + kw) * 2 + 1];
            float tr = tw[(h * m1t2 + kk) * 2];
            float ti = tw[(h * m1t2 + kk) * 2 + 1];
            zr += fr * tr + fi * ti;
            zi += fi * tr - fr * ti;
        }
        size_t oo = ((size_t)bo * H * m2 + e) * 2;
        g_Z[oo]     = zr * invHW;
        g_Z[oo + 1] = zi * invHW;
    }
}

// ------- fused GEMM: out = gelu(conv1x1 + bias + invW(Z)) --------------------
// block: 64 output channels x 64 contiguous pixels (one h row segment)
__global__ void k_fuse(const float* __restrict__ xin, int Ci, int Co,
                       int H, int W, int m2, const float* __restrict__ tw,
                       const float* __restrict__ cw, const float* __restrict__ cb,
                       float* __restrict__ out) {
    __shared__ float xs[32][65];
    __shared__ float ws[64][33];
    __shared__ float zs[64][24];
    __shared__ float tws[64][24];

    const int HW = H * W;
    int tilesPerImg = HW / 64;
    int b  = blockIdx.x / tilesPerImg;
    int p0 = (blockIdx.x % tilesPerImg) * 64;
    int ob = blockIdx.y * 64;
    int h  = p0 / W, w0 = p0 % W;
    int tid = threadIdx.x;
    int ty = tid >> 4, tx = tid & 15;

    float acc[4][4];
    #pragma unroll
    for (int r = 0; r < 4; r++)
        #pragma unroll
        for (int c = 0; c < 4; c++) acc[r][c] = 0.f;

    for (int ci0 = 0; ci0 < Ci; ci0 += 32) {
        for (int l = tid; l < 32 * 64; l += 256) {
            int i = l >> 6, p = l & 63;
            xs[i][p] = xin[(size_t)(b * Ci + ci0 + i) * HW + p0 + p];
        }
        for (int l = tid; l < 64 * 32; l += 256) {
            int o = l >> 5, i = l & 31;
            int oo = ob + o;
            ws[o][i] = (oo < Co) ? cw[(size_t)oo * Ci + ci0 + i] : 0.f;
        }
        __syncthreads();
        #pragma unroll
        for (int i = 0; i < 32; i++) {
            float xr_[4], wr_[4];
            #pragma unroll
            for (int c = 0; c < 4; c++) xr_[c] = xs[i][tx + 16 * c];
            #pragma unroll
            for (int r = 0; r < 4; r++) wr_[r] = ws[ty + 16 * r][i];
            #pragma unroll
            for (int r = 0; r < 4; r++)
                #pragma unroll
                for (int c = 0; c < 4; c++) acc[r][c] += wr_[r] * xr_[c];
        }
        __syncthreads();
    }

    // spectral tiles: z rows (prescaled x2 for kw>0), tw rows per pixel
    int m2c = 2 * m2;
    for (int l = tid; l < 64 * m2c; l += 256) {
        int o = l / m2c, r = l % m2c;
        int oo = ob + o;
        float v = (oo < Co) ? g_Z[(((size_t)(b * Co + oo) * H + h) * m2) * 2 + r] : 0.f;
        zs[o][r] = (r >= 2) ? 2.0f * v : v;
    }
    for (int l = tid; l < 64 * m2c; l += 256) {
        int p = l / m2c, r = l % m2c;
        tws[p][r] = tw[(size_t)(w0 + p) * m2c + r];
    }
    __syncthreads();

    #pragma unroll
    for (int r = 0; r < 4; r++) {
        int o_l = ty + 16 * r;
        int oo = ob + o_l;
        if (oo >= Co) continue;
        float bias = cb[oo];
        #pragma unroll
        for (int c = 0; c < 4; c++) {
            int p_l = tx + 16 * c;
            float spec = 0.f;
            for (int kw = 0; kw < m2; kw++) {
                spec += zs[o_l][2 * kw] * tws[p_l][2 * kw]
                      + zs[o_l][2 * kw + 1] * tws[p_l][2 * kw + 1];
            }
            out[(size_t)(b * Co + oo) * HW + p0 + p_l] = gelu_f(acc[r][c] + bias + spec);
        }
    }
}

// ---------------- 2x2 mean pool ----------------------------------------------
__global__ void k_pool(const float* __restrict__ in, int total, int H, int W,
                       float* __restrict__ out) {
    int idx = blockIdx.x * blockDim.x + threadIdx.x;
    if (idx >= total) return;
    int Ho = H / 2, Wo = W / 2;
    int wo = idx % Wo;
    int ho = (idx / Wo) % Ho;
    int bc = idx / (Wo * Ho);
    const float* p = in + ((size_t)bc * H + 2 * ho) * W + 2 * wo;
    out[idx] = 0.25f * (p[0] + p[1] + p[W] + p[W + 1]);
}

// ---------------- bilinear 2x upsample (half-pixel) into concat dst ----------
__global__ void k_up(const float* __restrict__ in, int total, int C, int H, int W,
                     float* __restrict__ dst, int Ct, int coff) {
    int idx = blockIdx.x * blockDim.x + threadIdx.x;
    if (idx >= total) return;
    int Ho = 2 * H, Wo = 2 * W;
    int wo = idx % Wo;
    int ho = (idx / Wo) % Ho;
    int c  = (idx / (Wo * Ho)) % C;
    int b  = idx / (Wo * Ho * C);

    int kh = ho >> 1, ha, hb; float wha, whb;
    if (ho & 1) { ha = kh; hb = (kh + 1 < H) ? kh + 1 : H - 1; wha = 0.75f; whb = 0.25f; }
    else        { ha = (kh - 1 >= 0) ? kh - 1 : 0; hb = kh;    wha = 0.25f; whb = 0.75f; }
    int kw = wo >> 1, wa, wb; float wwa, wwb;
    if (wo & 1) { wa = kw; wb = (kw + 1 < W) ? kw + 1 : W - 1; wwa = 0.75f; wwb = 0.25f; }
    else        { wa = (kw - 1 >= 0) ? kw - 1 : 0; wb = kw;    wwa = 0.25f; wwb = 0.75f; }

    const float* base = in + (size_t)(b * C + c) * H * W;
    float v = wha * (wwa * base[(size_t)ha * W + wa] + wwb * base[(size_t)ha * W + wb])
            + whb * (wwa * base[(size_t)hb * W + wa] + wwb * base[(size_t)hb * W + wb]);
    dst[((size_t)(b * Ct + coff + c) * Ho + ho) * Wo + wo] = v;
}

// ---------------- channel-block copy for concat ------------------------------
__global__ void k_copych(const float* __restrict__ in, int total, int C, int HW,
                         float* __restrict__ dst, int Ct, int coff) {
    int idx = blockIdx.x * blockDim.x + threadIdx.x;
    if (idx >= total) return;
    int p = idx % HW;
    int c = (idx / HW) % C;
    int b = idx / (HW * C);
    dst[((size_t)(b * Ct + coff + c)) * HW + p] = in[idx];
}

// ------- head: fc1(64->256)+gelu+fc2(256->3), GEMM-tiled ---------------------
// block: 64 pixels; o in 4 chunks of 64; fc2 reduced in smem
__global__ void k_head(const float* __restrict__ xin, const float* __restrict__ w1,
                       const float* __restrict__ b1, const float* __restrict__ w2,
                       const float* __restrict__ b2, float* __restrict__ out) {
    __shared__ float xs[64][65];
    __shared__ float ws[64][65];
    __shared__ float red[16][208];

    const int HW = 256 * 256;
    int b  = blockIdx.x >> 10;                   // HW/64 = 1024 tiles per image
    int p0 = (blockIdx.x & 1023) * 64;
    int tid = threadIdx.x;
    int ty = tid >> 4, tx = tid & 15;

    for (int l = tid; l < 64 * 64; l += 256) {
        int i = l >> 6, p = l & 63;
        xs[i][p] = xin[(size_t)(b * 64 + i) * HW + p0 + p];
    }

    float o3[3][4];
    #pragma unroll
    for (int cc = 0; cc < 3; cc++)
        #pragma unroll
        for (int c = 0; c < 4; c++) o3[cc][c] = 0.f;

    for (int oc = 0; oc < 4; oc++) {
        __syncthreads();
        for (int l = tid; l < 64 * 64; l += 256) {
            int o = l >> 6, i = l & 63;
            ws[o][i] = w1[(size_t)(oc * 64 + o) * 64 + i];
        }
        __syncthreads();

        float acc[4][4];
        #pragma unroll
        for (int r = 0; r < 4; r++) {
            float bb = b1[oc * 64 + ty + 16 * r];
            #pragma unroll
            for (int c = 0; c < 4; c++) acc[r][c] = bb;
        }
        #pragma unroll
        for (int i = 0; i < 64; i++) {
            float xr_[4], wr_[4];
            #pragma unroll
            for (int c = 0; c < 4; c++) xr_[c] = xs[i][tx + 16 * c];
            #pragma unroll
            for (int r = 0; r < 4; r++) wr_[r] = ws[ty + 16 * r][i];
            #pragma unroll
            for (int r = 0; r < 4; r++)
                #pragma unroll
                for (int c = 0; c < 4; c++) acc[r][c] += wr_[r] * xr_[c];
        }
        #pragma unroll
        for (int r = 0; r < 4; r++) {
            int o = oc * 64 + ty + 16 * r;
            float w20 = w2[o], w21 = w2[256 + o], w22 = w2[512 + o];
            #pragma unroll
            for (int c = 0; c < 4; c++) {
                float hh = gelu_f(acc[r][c]);
                o3[0][c] += hh * w20;
                o3[1][c] += hh * w21;
                o3[2][c] += hh * w22;
            }
        }
    }

    __syncthreads();
    #pragma unroll
    for (int c = 0; c < 4; c++) {
        int p = tx + 16 * c;
        red[ty][p * 3 + 0] = o3[0][c];
        red[ty][p * 3 + 1] = o3[1][c];
        red[ty][p * 3 + 2] = o3[2][c];
    }
    __syncthreads();
    if (tid < 192) {
        int p = tid / 3, cc = tid % 3;
        float s = b2[cc];
        #pragma unroll
        for (int t = 0; t < 16; t++) s += red[t][p * 3 + cc];
        out[((size_t)b * HW + p0 + p) * 3 + cc] = s;
    }
}

// =============================================================================
static inline int grid_of(int total) { return (total + 255) / 256; }

static void spectral_block(const float* xin, int Ci, int Co, int H, int m1,
                           const float* w1, const float* w2,
                           const float* cw, const float* cb,
                           const float* twW, const float* twH, float* out) {
    const int W = H, m2 = m1, m1t2 = 2 * m1;
    int rows = BSZ * Ci * H;
    k_fwd_w<<<rows / 32, 256>>>(xin, rows, W, m2, twW);
    k_fwd_h<<<BSZ * Ci, 256>>>(H, m1, m2, twH);
    k_mix<<<BSZ * m1t2, 256>>>(Ci, Co, m1, m2, w1, w2);
    k_inv_h<<<BSZ * Co, 256>>>(H, m1, m2, twH, 1.0f / (float)(H * W));
    dim3 fg(BSZ * H * W / 64, (Co + 63) / 64);
    k_fuse<<<fg, 256>>>(xin, Ci, Co, H, W, m2, twW, cw, cb, out);
}

extern "C" void kernel_launch(void* const* d_in, const int* in_sizes, int n_in,
                              void* d_out, int out_size) {
    const float* x      = (const float*)d_in[0];
    const float* fcin_w = (const float*)d_in[1];
    const float* fcin_b = (const float*)d_in[2];
    const float* sc1_w1 = (const float*)d_in[3];
    const float* sc1_w2 = (const float*)d_in[4];
    const float* c1_w   = (const float*)d_in[5];
    const float* c1_b   = (const float*)d_in[6];
    const float* sc2_w1 = (const float*)d_in[7];
    const float* sc2_w2 = (const float*)d_in[8];
    const float* c2_w   = (const float*)d_in[9];
    const float* c2_b   = (const float*)d_in[10];
    const float* scb_w1 = (const float*)d_in[11];
    const float* scb_w2 = (const float*)d_in[12];
    const float* cb_w   = (const float*)d_in[13];
    const float* cb_b   = (const float*)d_in[14];
    const float* su2_w1 = (const float*)d_in[15];
    const float* su2_w2 = (const float*)d_in[16];
    const float* u2_w   = (const float*)d_in[17];
    const float* u2_b   = (const float*)d_in[18];
    const float* su1_w1 = (const float*)d_in[19];
    const float* su1_w2 = (const float*)d_in[20];
    const float* u1_w   = (const float*)d_in[21];
    const float* u1_b   = (const float*)d_in[22];
    const float* fc1_w  = (const float*)d_in[23];
    const float* fc1_b  = (const float*)d_in[24];
    const float* fc2_w  = (const float*)d_in[25];
    const float* fc2_b  = (const float*)d_in[26];

    float *p_v, *p_x1, *p_x1d, *p_x2, *p_x2d, *p_xb, *p_x2c, *p_x2o, *p_x1c, *p_x1o, *p_tw;
    cudaGetSymbolAddress((void**)&p_v,   g_v);
    cudaGetSymbolAddress((void**)&p_x1,  g_x1);
    cudaGetSymbolAddress((void**)&p_x1d, g_x1d);
    cudaGetSymbolAddress((void**)&p_x2,  g_x2);
    cudaGetSymbolAddress((void**)&p_x2d, g_x2d);
    cudaGetSymbolAddress((void**)&p_xb,  g_xb);
    cudaGetSymbolAddress((void**)&p_x2c, g_x2c);
    cudaGetSymbolAddress((void**)&p_x2o, g_x2o);
    cudaGetSymbolAddress((void**)&p_x1c, g_x1c);
    cudaGetSymbolAddress((void**)&p_x1o, g_x1o);
    cudaGetSymbolAddress((void**)&p_tw,  g_tw);

    const float* tw_W0 = p_tw + 2 * TW0;
    const float* tw_H0 = p_tw + 2 * TH0;
    const float* tw_W1 = p_tw + 2 * TW1;
    const float* tw_H1 = p_tw + 2 * TH1;
    const float* tw_W2 = p_tw + 2 * TW2;
    const float* tw_H2 = p_tw + 2 * TH2;

    k_init_tw<<<32, 256>>>();

    // lift 6 -> 64
    {
        int t = BSZ * 64 * 256 * 256;
        k_lift<<<grid_of(t), 256>>>(x, fcin_w, fcin_b);
    }

    // encoder level 1: 64 -> 64 @ 256
    spectral_block(p_v, 64, 64, 256, 12, sc1_w1, sc1_w2, c1_w, c1_b, tw_W0, tw_H0, p_x1);
    {
        int t = BSZ * 64 * 128 * 128;
        k_pool<<<grid_of(t), 256>>>(p_x1, t, 256, 256, p_x1d);
    }

    // encoder level 2: 64 -> 96 @ 128
    spectral_block(p_x1d, 64, 96, 128, 8, sc2_w1, sc2_w2, c2_w, c2_b, tw_W1, tw_H1, p_x2);
    {
        int t = BSZ * 96 * 64 * 64;
        k_pool<<<grid_of(t), 256>>>(p_x2, t, 128, 128, p_x2d);
    }

    // bottleneck: 96 -> 128 @ 64
    spectral_block(p_x2d, 96, 128, 64, 4, scb_w1, scb_w2, cb_w, cb_b, tw_W2, tw_H2, p_xb);

    // x2c = concat(up(xb), x2) -> [4,224,128,128]
    {
        int t = BSZ * 128 * 128 * 128;
        k_up<<<grid_of(t), 256>>>(p_xb, t, 128, 64, 64, p_x2c, 224, 0);
        t = BSZ * 96 * 128 * 128;
        k_copych<<<grid_of(t), 256>>>(p_x2, t, 96, 128 * 128, p_x2c, 224, 128);
    }

    // decoder level 2: 224 -> 96 @ 128
    spectral_block(p_x2c, 224, 96, 128, 8, su2_w1, su2_w2, u2_w, u2_b, tw_W1, tw_H1, p_x2o);

    // x1c = concat(up(x2o), x1) -> [4,160,256,256]
    {
        int t = BSZ * 96 * 256 * 256;
        k_up<<<grid_of(t), 256>>>(p_x2o, t, 96, 128, 128, p_x1c, 160, 0);
        t = BSZ * 64 * 256 * 256;
        k_copych<<<grid_of(t), 256>>>(p_x1, t, 64, 256 * 256, p_x1c, 160, 96);
    }

    // decoder level 1: 160 -> 64 @ 256
    spectral_block(p_x1c, 160, 64, 256, 12, su1_w1, su1_w2, u1_w, u1_b, tw_W0, tw_H0, p_x1o);

    // head: fc1 + gelu + fc2 fused
    k_head<<<BSZ * 1024, 256>>>(p_x1o, fc1_w, fc1_b, fc2_w, fc2_b, (float*)d_out);
}

// round 3
// speedup vs baseline: 1.7785x; 1.1969x over previous
#include <cuda_runtime.h>
#include <math.h>

#define BSZ 4

// ---------------- scratch (device globals; no allocations allowed) ----------
__device__ float g_v  [16777216];   // [4,64,256,256]
__device__ float g_x1 [16777216];   // [4,64,256,256]
__device__ float g_x1d[ 4194304];   // [4,64,128,128]
__device__ float g_x2 [ 6291456];   // [4,96,128,128]
__device__ float g_x2d[ 1572864];   // [4,96,64,64]
__device__ float g_xb [ 2097152];   // [4,128,64,64]
__device__ float g_x2c[14680064];   // [4,224,128,128]
__device__ float g_x2o[ 6291456];   // [4,96,128,128]
__device__ float g_x1c[41943040];   // [4,160,256,256]
__device__ float g_x1o[16777216];   // [4,64,256,256]

__device__ float g_XW [ 3932160];   // transposed: [H][BC*m2c]
__device__ float g_XF [  368640];   // [BC,2m1,m2] complex
__device__ float g_OF [  368640];   // [B,Co,2m1,m2] complex
__device__ float g_Z  [ 1572864];   // [B,Co,H,m2] complex (scaled)
__device__ float g_tw [   26112];   // twiddle tables (complex interleaved)

#define TW0 0
#define TH0 3072
#define TW1 9216
#define TH1 10240
#define TW2 12288
#define TH2 12544

__device__ __forceinline__ float gelu_f(float x) {
    return 0.5f * x * (1.0f + erff(x * 0.70710678118654752f));
}

// ---------------- twiddle init -----------------------------------------------
__global__ void k_init_tw() {
    const int cfg[3][5] = {{256,12,12,TW0,TH0},{128,8,8,TW1,TH1},{64,4,4,TW2,TH2}};
    int tid = blockIdx.x * blockDim.x + threadIdx.x;
    int nth = gridDim.x * blockDim.x;
    for (int c = 0; c < 3; c++) {
        int H = cfg[c][0], m1 = cfg[c][1], m2 = cfg[c][2];
        int offW = cfg[c][3], offH = cfg[c][4];
        int nW = H * m2;
        for (int e = tid; e < nW; e += nth) {
            int w = e / m2, kw = e % m2;
            int p = (w * kw) % H;
            double s, co; sincos(2.0 * 3.14159265358979323846 * (double)p / (double)H, &s, &co);
            g_tw[(offW + e) * 2]     = (float)co;
            g_tw[(offW + e) * 2 + 1] = (float)(-s);
        }
        int m1t2 = 2 * m1;
        int nH = H * m1t2;
        for (int e = tid; e < nH; e += nth) {
            int h = e / m1t2, j = e % m1t2;
            int kh = (j < m1) ? j : (H - 2 * m1 + j);
            int p = (kh * h) % H;
            double s, co; sincos(2.0 * 3.14159265358979323846 * (double)p / (double)H, &s, &co);
            g_tw[(offH + e) * 2]     = (float)co;
            g_tw[(offH + e) * 2 + 1] = (float)(-s);
        }
    }
}

// ---------------- lift: x[B,H,W,6] -> v[B,64,H,W] ----------------------------
__global__ void k_lift(const float* __restrict__ x, const float* __restrict__ w,
                       const float* __restrict__ b) {
    const int HW = 256 * 256;
    int idx = blockIdx.x * blockDim.x + threadIdx.x;
    if (idx >= BSZ * 64 * HW) return;
    int p  = idx % HW;
    int c  = (idx / HW) % 64;
    int bb = idx / (HW * 64);
    const float* xp = x + ((size_t)bb * HW + p) * 6;
    float acc = b[c];
    #pragma unroll
    for (int i = 0; i < 6; i++) acc += xp[i] * w[c * 6 + i];
    g_v[idx] = acc;
}

// ------- fwd DFT along W: x rows -> XWt[h][bc*m2c] (transposed) -------------
// 64 rows / block; thread: 2 rows x 3 kc outputs.
__global__ void k_fwd_w(const float* __restrict__ xin, int H, int W, int m2,
                        const float* __restrict__ tw, int BC) {
    __shared__ float xs[64][65];
    __shared__ float tws[64][24];
    int m2c = 2 * m2;
    int r0 = blockIdx.x * 64;
    int tid = threadIdx.x;
    int row_l = tid & 31;
    int kc0 = tid >> 5;                 // 0..7 (warp-uniform)
    bool v1 = (kc0 + 8 < m2c), v2 = (kc0 + 16 < m2c);
    float a00 = 0.f, a01 = 0.f, a02 = 0.f, a10 = 0.f, a11 = 0.f, a12 = 0.f;

    for (int k0 = 0; k0 < W; k0 += 64) {
        for (int l = tid; l < 64 * 16; l += 256) {
            int r = l >> 4, k4 = (l & 15) * 4;
            float4 v = *(const float4*)(xin + (size_t)(r0 + r) * W + k0 + k4);
            xs[r][k4] = v.x; xs[r][k4 + 1] = v.y; xs[r][k4 + 2] = v.z; xs[r][k4 + 3] = v.w;
        }
        for (int l = tid; l < 64 * m2c; l += 256) {
            int k = l / m2c, kc = l % m2c;
            tws[k][kc] = tw[(size_t)(k0 + k) * m2c + kc];
        }
        __syncthreads();
        #pragma unroll 4
        for (int k = 0; k < 64; k++) {
            float x0 = xs[row_l][k];
            float x1 = xs[row_l + 32][k];
            float t0 = tws[k][kc0];
            a00 += x0 * t0; a10 += x1 * t0;
            if (v1) { float t1 = tws[k][kc0 + 8];  a01 += x0 * t1; a11 += x1 * t1; }
            if (v2) { float t2 = tws[k][kc0 + 16]; a02 += x0 * t2; a12 += x1 * t2; }
        }
        __syncthreads();
    }
    int r = r0 + row_l;
    int bc = r / H, h = r - bc * H;
    size_t base = ((size_t)h * BC + bc) * m2c;
    g_XW[base + kc0] = a00;
    if (v1) g_XW[base + kc0 + 8]  = a01;
    if (v2) g_XW[base + kc0 + 16] = a02;
    r = r0 + row_l + 32;
    bc = r / H; h = r - bc * H;
    base = ((size_t)h * BC + bc) * m2c;
    g_XW[base + kc0] = a10;
    if (v1) g_XW[base + kc0 + 8]  = a11;
    if (v2) g_XW[base + kc0 + 16] = a12;
}

// ------- fwd DFT along H as GEMM over transposed XW --------------------------
// block: 32 complex columns x all 2m1 modes; thread: 1 col x up to 3 modes.
__global__ void k_fwd_h(int H, int BCm2, int m1, int m2, const float* __restrict__ tw) {
    __shared__ float xs[64][64];
    __shared__ float tws[64][48];
    int m1t2 = 2 * m1;
    int cc0 = blockIdx.x * 32;
    int tid = threadIdx.x;
    int cl = tid & 31;
    int g  = tid >> 5;          // 0..7 (warp-uniform)
    bool v1 = (g + 8 < m1t2), v2 = (g + 16 < m1t2);
    float ar0 = 0.f, ai0 = 0.f, ar1 = 0.f, ai1 = 0.f, ar2 = 0.f, ai2 = 0.f;
    int N2 = BCm2 * 2;

    for (int h0 = 0; h0 < H; h0 += 64) {
        for (int l = tid; l < 64 * 16; l += 256) {
            int hh = l >> 4, c4 = (l & 15) * 4;
            *(float4*)&xs[hh][c4] =
                *(const float4*)(g_XW + (size_t)(h0 + hh) * N2 + cc0 * 2 + c4);
        }
        for (int l = tid; l < 64 * m1t2 * 2; l += 256) {
            int hh = l / (m1t2 * 2), c = l % (m1t2 * 2);
            tws[hh][c] = tw[(size_t)(h0 + hh) * m1t2 * 2 + c];
        }
        __syncthreads();
        #pragma unroll 4
        for (int hh = 0; hh < 64; hh++) {
            float2 xv = *(const float2*)&xs[hh][2 * cl];
            float tr = tws[hh][2 * g], ti = tws[hh][2 * g + 1];
            ar0 += xv.x * tr - xv.y * ti;
            ai0 += xv.x * ti + xv.y * tr;
            if (v1) {
                float tr1 = tws[hh][2 * (g + 8)], ti1 = tws[hh][2 * (g + 8) + 1];
                ar1 += xv.x * tr1 - xv.y * ti1;
                ai1 += xv.x * ti1 + xv.y * tr1;
            }
            if (v2) {
                float tr2 = tws[hh][2 * (g + 16)], ti2 = tws[hh][2 * (g + 16) + 1];
                ar2 += xv.x * tr2 - xv.y * ti2;
                ai2 += xv.x * ti2 + xv.y * tr2;
            }
        }
        __syncthreads();
    }
    int cc = cc0 + cl, bc = cc / m2, kw = cc % m2;
    size_t oo = (((size_t)bc * m1t2 + g) * m2 + kw) * 2;
    g_XF[oo] = ar0; g_XF[oo + 1] = ai0;
    if (v1) { oo = (((size_t)bc * m1t2 + g + 8) * m2 + kw) * 2;  g_XF[oo] = ar1; g_XF[oo + 1] = ai1; }
    if (v2) { oo = (((size_t)bc * m1t2 + g + 16) * m2 + kw) * 2; g_XF[oo] = ar2; g_XF[oo + 1] = ai2; }
}

// ------- per-mode channel mix: block = (b, kk); 4-way interleaved outputs ----
__global__ void k_mix(int Ci, int Co, int m1, int m2,
                      const float* __restrict__ w1, const float* __restrict__ w2) {
    __shared__ float xf_s[3840];        // Ci * 2*m2 (max 160*24 / 224*16)
    int m1t2 = 2 * m1, m2c = 2 * m2;
    int kk = blockIdx.x % m1t2;
    int b  = blockIdx.x / m1t2;
    int tid = threadIdx.x;

    for (int l = tid; l < Ci * m2c; l += 256) {
        int i = l / m2c, kc = l % m2c;
        xf_s[l] = g_XF[(((size_t)(b * Ci + i) * m1t2 + kk) * m2) * 2 + kc];
    }
    __syncthreads();

    int kkr = (kk < m1) ? kk : kk - m1;
    const float* wsel = (kk < m1) ? w1 : w2;
    int wstride = Co * m1 * m2 * 2;
    int nout = Co * m2;
    for (int e0 = tid; e0 < nout; e0 += 1024) {
        float orr[4] = {0,0,0,0}, oii[4] = {0,0,0,0};
        int xoff[4], woff[4]; bool val[4];
        #pragma unroll
        for (int u = 0; u < 4; u++) {
            int e = e0 + 256 * u;
            val[u] = (e < nout);
            int kw = val[u] ? e % m2 : 0;
            int o  = val[u] ? e / m2 : 0;
            xoff[u] = 2 * kw;
            woff[u] = ((o * m1 + kkr) * m2 + kw) * 2;
        }
        for (int i = 0; i < Ci; i++) {
            const float* wrow = wsel + (size_t)i * wstride;
            const float* xrow = xf_s + i * m2c;
            #pragma unroll
            for (int u = 0; u < 4; u++) {
                float xr = xrow[xoff[u]], xi = xrow[xoff[u] + 1];
                float wr = wrow[woff[u]], wi = wrow[woff[u] + 1];
                orr[u] += xr * wr - xi * wi;
                oii[u] += xr * wi + xi * wr;
            }
        }
        #pragma unroll
        for (int u = 0; u < 4; u++) {
            if (val[u]) {
                int e = e0 + 256 * u;
                int kw = e % m2, o = e / m2;
                size_t oo = (((size_t)(b * Co + o) * m1t2 + kk) * m2 + kw) * 2;
                g_OF[oo] = orr[u]; g_OF[oo + 1] = oii[u];
            }
        }
    }
}

// ------- inverse DFT along H: per-bo block; 2-way interleaved ----------------
__global__ void k_inv_h(int H, int m1, int m2, const float* __restrict__ tw,
                        float invHW) {
    __shared__ float of_s[1152];
    int bo = blockIdx.x;
    int tid = threadIdx.x;
    int m1t2 = 2 * m1;
    int nload = m1t2 * m2 * 2;
    const float* src = g_OF + (size_t)bo * nload;
    for (int l = tid; l < nload; l += 256) of_s[l] = src[l];
    __syncthreads();

    int nout = H * m2;
    for (int e = tid; e < nout; e += 512) {
        int e2 = e + 256;
        bool v2 = (e2 < nout);
        int kw0 = e % m2, h0 = e / m2;
        int kw1 = v2 ? e2 % m2 : 0, h1 = v2 ? e2 / m2 : 0;
        float zr0 = 0.f, zi0 = 0.f, zr1 = 0.f, zi1 = 0.f;
        for (int kk = 0; kk < m1t2; kk++) {
            float tr0 = tw[(h0 * m1t2 + kk) * 2], ti0 = tw[(h0 * m1t2 + kk) * 2 + 1];
            float fr0 = of_s[(kk * m2 + kw0) * 2], fi0 = of_s[(kk * m2 + kw0) * 2 + 1];
            zr0 += fr0 * tr0 + fi0 * ti0;
            zi0 += fi0 * tr0 - fr0 * ti0;
            float tr1 = tw[(h1 * m1t2 + kk) * 2], ti1 = tw[(h1 * m1t2 + kk) * 2 + 1];
            float fr1 = of_s[(kk * m2 + kw1) * 2], fi1 = of_s[(kk * m2 + kw1) * 2 + 1];
            zr1 += fr1 * tr1 + fi1 * ti1;
            zi1 += fi1 * tr1 - fr1 * ti1;
        }
        size_t oo = ((size_t)bo * nout + e) * 2;
        g_Z[oo] = zr0 * invHW; g_Z[oo + 1] = zi0 * invHW;
        if (v2) {
            oo = ((size_t)bo * nout + e2) * 2;
            g_Z[oo] = zr1 * invHW; g_Z[oo + 1] = zi1 * invHW;
        }
    }
}

// ------- fused GEMM: out = gelu(conv1x1 + bias + invW(Z)) --------------------
// 64 ch x 64 px tile, contiguous 4x4 microtile, vectorized smem
__global__ void k_fuse(const float* __restrict__ xin, int Ci, int Co,
                       int H, int W, int m2, const float* __restrict__ tw,
                       const float* __restrict__ cw, const float* __restrict__ cb,
                       float* __restrict__ out) {
    __shared__ float xs[32][68];
    __shared__ float wst[32][68];   // [i][o]
    __shared__ float zs[64][25];
    __shared__ float tws[64][25];

    const int HW = H * W;
    int tilesPerImg = HW >> 6;
    int b  = blockIdx.x / tilesPerImg;
    int p0 = (blockIdx.x % tilesPerImg) << 6;
    int ob = blockIdx.y << 6;
    int h  = p0 / W, w0 = p0 % W;
    int tid = threadIdx.x;
    int ty = tid >> 4, tx = tid & 15;

    float acc[4][4];
    #pragma unroll
    for (int r = 0; r < 4; r++)
        #pragma unroll
        for (int c = 0; c < 4; c++) acc[r][c] = 0.f;

    for (int ci0 = 0; ci0 < Ci; ci0 += 32) {
        for (int l = tid; l < 512; l += 256) {
            int i = l >> 4, p4 = (l & 15) * 4;
            float4 v = *(const float4*)(xin + (size_t)(b * Ci + ci0 + i) * HW + p0 + p4);
            *(float4*)&xs[i][p4] = v;
        }
        for (int l = tid; l < 2048; l += 256) {
            int o = l >> 5, i = l & 31;
            int oo = ob + o;
            wst[i][o] = (oo < Co) ? cw[(size_t)oo * Ci + ci0 + i] : 0.f;
        }
        __syncthreads();
        #pragma unroll
        for (int i = 0; i < 32; i++) {
            float4 xv = *(const float4*)&xs[i][tx * 4];
            float4 wv = *(const float4*)&wst[i][ty * 4];
            acc[0][0] += wv.x * xv.x; acc[0][1] += wv.x * xv.y;
            acc[0][2] += wv.x * xv.z; acc[0][3] += wv.x * xv.w;
            acc[1][0] += wv.y * xv.x; acc[1][1] += wv.y * xv.y;
            acc[1][2] += wv.y * xv.z; acc[1][3] += wv.y * xv.w;
            acc[2][0] += wv.z * xv.x; acc[2][1] += wv.z * xv.y;
            acc[2][2] += wv.z * xv.z; acc[2][3] += wv.z * xv.w;
            acc[3][0] += wv.w * xv.x; acc[3][1] += wv.w * xv.y;
            acc[3][2] += wv.w * xv.z; acc[3][3] += wv.w * xv.w;
        }
        __syncthreads();
    }

    int m2c = 2 * m2;
    for (int l = tid; l < 64 * m2c; l += 256) {
        int o = l / m2c, r = l % m2c;
        int oo = ob + o;
        float v = (oo < Co) ? g_Z[(((size_t)(b * Co + oo) * H + h) * m2) * 2 + r] : 0.f;
        zs[o][r] = (r >= 2) ? 2.0f * v : v;
    }
    for (int l = tid; l < 64 * m2c; l += 256) {
        int p = l / m2c, r = l % m2c;
        tws[p][r] = tw[(size_t)(w0 + p) * m2c + r];
    }
    __syncthreads();

    #pragma unroll
    for (int r = 0; r < 4; r++) {
        int o_l = ty * 4 + r;
        int oo = ob + o_l;
        if (oo >= Co) continue;
        float bias = cb[oo];
        float4 ov;
        float res[4];
        #pragma unroll
        for (int c = 0; c < 4; c++) {
            int p_l = tx * 4 + c;
            float spec = 0.f;
            for (int kw = 0; kw < m2; kw++) {
                spec += zs[o_l][2 * kw] * tws[p_l][2 * kw]
                      + zs[o_l][2 * kw + 1] * tws[p_l][2 * kw + 1];
            }
            res[c] = gelu_f(acc[r][c] + bias + spec);
        }
        ov.x = res[0]; ov.y = res[1]; ov.z = res[2]; ov.w = res[3];
        *(float4*)(out + (size_t)(b * Co + oo) * HW + p0 + tx * 4) = ov;
    }
}

// ---------------- 2x2 mean pool ----------------------------------------------
__global__ void k_pool(const float* __restrict__ in, int total, int H, int W,
                       float* __restrict__ out) {
    int idx = blockIdx.x * blockDim.x + threadIdx.x;
    if (idx >= total) return;
    int Ho = H / 2, Wo = W / 2;
    int wo = idx % Wo;
    int ho = (idx / Wo) % Ho;
    int bc = idx / (Wo * Ho);
    const float* p = in + ((size_t)bc * H + 2 * ho) * W + 2 * wo;
    out[idx] = 0.25f * (p[0] + p[1] + p[W] + p[W + 1]);
}

// ---------------- bilinear 2x upsample (half-pixel) into concat dst ----------
__global__ void k_up(const float* __restrict__ in, int total, int C, int H, int W,
                     float* __restrict__ dst, int Ct, int coff) {
    int idx = blockIdx.x * blockDim.x + threadIdx.x;
    if (idx >= total) return;
    int Ho = 2 * H, Wo = 2 * W;
    int wo = idx % Wo;
    int ho = (idx / Wo) % Ho;
    int c  = (idx / (Wo * Ho)) % C;
    int b  = idx / (Wo * Ho * C);

    int kh = ho >> 1, ha, hb; float wha, whb;
    if (ho & 1) { ha = kh; hb = (kh + 1 < H) ? kh + 1 : H - 1; wha = 0.75f; whb = 0.25f; }
    else        { ha = (kh - 1 >= 0) ? kh - 1 : 0; hb = kh;    wha = 0.25f; whb = 0.75f; }
    int kw = wo >> 1, wa, wb; float wwa, wwb;
    if (wo & 1) { wa = kw; wb = (kw + 1 < W) ? kw + 1 : W - 1; wwa = 0.75f; wwb = 0.25f; }
    else        { wa = (kw - 1 >= 0) ? kw - 1 : 0; wb = kw;    wwa = 0.25f; wwb = 0.75f; }

    const float* base = in + (size_t)(b * C + c) * H * W;
    float v = wha * (wwa * base[(size_t)ha * W + wa] + wwb * base[(size_t)ha * W + wb])
            + whb * (wwa * base[(size_t)hb * W + wa] + wwb * base[(size_t)hb * W + wb]);
    dst[((size_t)(b * Ct + coff + c) * Ho + ho) * Wo + wo] = v;
}

// ---------------- channel-block copy for concat ------------------------------
__global__ void k_copych(const float* __restrict__ in, int total, int C, int HW,
                         float* __restrict__ dst, int Ct, int coff) {
    int idx = blockIdx.x * blockDim.x + threadIdx.x;
    if (idx >= total) return;
    int p = idx % HW;
    int c = (idx / HW) % C;
    int b = idx / (HW * C);
    dst[((size_t)(b * Ct + coff + c)) * HW + p] = in[idx];
}

// ------- head: fc1(64->256)+gelu+fc2(256->3), GEMM-tiled ---------------------
__global__ void k_head(const float* __restrict__ xin, const float* __restrict__ w1,
                       const float* __restrict__ b1, const float* __restrict__ w2,
                       const float* __restrict__ b2, float* __restrict__ out) {
    __shared__ float xs[64][68];
    __shared__ float wst[64][68];   // [i][o]
    __shared__ float red[16][200];

    const int HW = 256 * 256;
    int b  = blockIdx.x >> 10;
    int p0 = (blockIdx.x & 1023) * 64;
    int tid = threadIdx.x;
    int ty = tid >> 4, tx = tid & 15;

    for (int l = tid; l < 64 * 16; l += 256) {
        int i = l >> 4, p4 = (l & 15) * 4;
        *(float4*)&xs[i][p4] =
            *(const float4*)(xin + (size_t)(b * 64 + i) * HW + p0 + p4);
    }

    float o3[3][4];
    #pragma unroll
    for (int cc = 0; cc < 3; cc++)
        #pragma unroll
        for (int c = 0; c < 4; c++) o3[cc][c] = 0.f;

    for (int oc = 0; oc < 4; oc++) {
        __syncthreads();
        for (int l = tid; l < 64 * 64; l += 256) {
            int o = l >> 6, i = l & 63;
            wst[i][o] = w1[(size_t)(oc * 64 + o) * 64 + i];
        }
        __syncthreads();

        float acc[4][4];
        #pragma unroll
        for (int r = 0; r < 4; r++) {
            float bb = b1[oc * 64 + ty * 4 + r];
            #pragma unroll
            for (int c = 0; c < 4; c++) acc[r][c] = bb;
        }
        #pragma unroll
        for (int i = 0; i < 64; i++) {
            float4 xv = *(const float4*)&xs[i][tx * 4];
            float4 wv = *(const float4*)&wst[i][ty * 4];
            acc[0][0] += wv.x * xv.x; acc[0][1] += wv.x * xv.y;
            acc[0][2] += wv.x * xv.z; acc[0][3] += wv.x * xv.w;
            acc[1][0] += wv.y * xv.x; acc[1][1] += wv.y * xv.y;
            acc[1][2] += wv.y * xv.z; acc[1][3] += wv.y * xv.w;
            acc[2][0] += wv.z * xv.x; acc[2][1] += wv.z * xv.y;
            acc[2][2] += wv.z * xv.z; acc[2][3] += wv.z * xv.w;
            acc[3][0] += wv.w * xv.x; acc[3][1] += wv.w * xv.y;
            acc[3][2] += wv.w * xv.z; acc[3][3] += wv.w * xv.w;
        }
        #pragma unroll
        for (int r = 0; r < 4; r++) {
            int o = oc * 64 + ty * 4 + r;
            float w20 = w2[o], w21 = w2[256 + o], w22 = w2[512 + o];
            #pragma unroll
            for (int c = 0; c < 4; c++) {
                float hh = gelu_f(acc[r][c]);
                o3[0][c] += hh * w20;
                o3[1][c] += hh * w21;
                o3[2][c] += hh * w22;
            }
        }
    }

    __syncthreads();
    #pragma unroll
    for (int c = 0; c < 4; c++) {
        int p = tx * 4 + c;
        red[ty][p * 3 + 0] = o3[0][c];
        red[ty][p * 3 + 1] = o3[1][c];
        red[ty][p * 3 + 2] = o3[2][c];
    }
    __syncthreads();
    if (tid < 192) {
        int p = tid / 3, cc = tid % 3;
        float s = b2[cc];
        #pragma unroll
        for (int t = 0; t < 16; t++) s += red[t][p * 3 + cc];
        out[((size_t)b * HW + p0 + p) * 3 + cc] = s;
    }
}

// =============================================================================
static inline int grid_of(int total) { return (total + 255) / 256; }

static void spectral_block(const float* xin, int Ci, int Co, int H, int m1,
                           const float* w1, const float* w2,
                           const float* cw, const float* cb,
                           const float* twW, const float* twH, float* out) {
    const int W = H, m2 = m1, m1t2 = 2 * m1;
    int BC = BSZ * Ci;
    k_fwd_w<<<BC * H / 64, 256>>>(xin, H, W, m2, twW, BC);
    k_fwd_h<<<BC * m2 / 32, 256>>>(H, BC * m2, m1, m2, twH);
    k_mix<<<BSZ * m1t2, 256>>>(Ci, Co, m1, m2, w1, w2);
    k_inv_h<<<BSZ * Co, 256>>>(H, m1, m2, twH, 1.0f / (float)(H * W));
    dim3 fg(BSZ * H * W / 64, (Co + 63) / 64);
    k_fuse<<<fg, 256>>>(xin, Ci, Co, H, W, m2, twW, cw, cb, out);
}

extern "C" void kernel_launch(void* const* d_in, const int* in_sizes, int n_in,
                              void* d_out, int out_size) {
    const float* x      = (const float*)d_in[0];
    const float* fcin_w = (const float*)d_in[1];
    const float* fcin_b = (const float*)d_in[2];
    const float* sc1_w1 = (const float*)d_in[3];
    const float* sc1_w2 = (const float*)d_in[4];
    const float* c1_w   = (const float*)d_in[5];
    const float* c1_b   = (const float*)d_in[6];
    const float* sc2_w1 = (const float*)d_in[7];
    const float* sc2_w2 = (const float*)d_in[8];
    const float* c2_w   = (const float*)d_in[9];
    const float* c2_b   = (const float*)d_in[10];
    const float* scb_w1 = (const float*)d_in[11];
    const float* scb_w2 = (const float*)d_in[12];
    const float* cb_w   = (const float*)d_in[13];
    const float* cb_b   = (const float*)d_in[14];
    const float* su2_w1 = (const float*)d_in[15];
    const float* su2_w2 = (const float*)d_in[16];
    const float* u2_w   = (const float*)d_in[17];
    const float* u2_b   = (const float*)d_in[18];
    const float* su1_w1 = (const float*)d_in[19];
    const float* su1_w2 = (const float*)d_in[20];
    const float* u1_w   = (const float*)d_in[21];
    const float* u1_b   = (const float*)d_in[22];
    const float* fc1_w  = (const float*)d_in[23];
    const float* fc1_b  = (const float*)d_in[24];
    const float* fc2_w  = (const float*)d_in[25];
    const float* fc2_b  = (const float*)d_in[26];

    float *p_v, *p_x1, *p_x1d, *p_x2, *p_x2d, *p_xb, *p_x2c, *p_x2o, *p_x1c, *p_x1o, *p_tw;
    cudaGetSymbolAddress((void**)&p_v,   g_v);
    cudaGetSymbolAddress((void**)&p_x1,  g_x1);
    cudaGetSymbolAddress((void**)&p_x1d, g_x1d);
    cudaGetSymbolAddress((void**)&p_x2,  g_x2);
    cudaGetSymbolAddress((void**)&p_x2d, g_x2d);
    cudaGetSymbolAddress((void**)&p_xb,  g_xb);
    cudaGetSymbolAddress((void**)&p_x2c, g_x2c);
    cudaGetSymbolAddress((void**)&p_x2o, g_x2o);
    cudaGetSymbolAddress((void**)&p_x1c, g_x1c);
    cudaGetSymbolAddress((void**)&p_x1o, g_x1o);
    cudaGetSymbolAddress((void**)&p_tw,  g_tw);

    const float* tw_W0 = p_tw + 2 * TW0;
    const float* tw_H0 = p_tw + 2 * TH0;
    const float* tw_W1 = p_tw + 2 * TW1;
    const float* tw_H1 = p_tw + 2 * TH1;
    const float* tw_W2 = p_tw + 2 * TW2;
    const float* tw_H2 = p_tw + 2 * TH2;

    k_init_tw<<<32, 256>>>();

    // lift 6 -> 64
    {
        int t = BSZ * 64 * 256 * 256;
        k_lift<<<grid_of(t), 256>>>(x, fcin_w, fcin_b);
    }

    // encoder level 1: 64 -> 64 @ 256
    spectral_block(p_v, 64, 64, 256, 12, sc1_w1, sc1_w2, c1_w, c1_b, tw_W0, tw_H0, p_x1);
    {
        int t = BSZ * 64 * 128 * 128;
        k_pool<<<grid_of(t), 256>>>(p_x1, t, 256, 256, p_x1d);
    }

    // encoder level 2: 64 -> 96 @ 128
    spectral_block(p_x1d, 64, 96, 128, 8, sc2_w1, sc2_w2, c2_w, c2_b, tw_W1, tw_H1, p_x2);
    {
        int t = BSZ * 96 * 64 * 64;
        k_pool<<<grid_of(t), 256>>>(p_x2, t, 128, 128, p_x2d);
    }

    // bottleneck: 96 -> 128 @ 64
    spectral_block(p_x2d, 96, 128, 64, 4, scb_w1, scb_w2, cb_w, cb_b, tw_W2, tw_H2, p_xb);

    // x2c = concat(up(xb), x2) -> [4,224,128,128]
    {
        int t = BSZ * 128 * 128 * 128;
        k_up<<<grid_of(t), 256>>>(p_xb, t, 128, 64, 64, p_x2c, 224, 0);
        t = BSZ * 96 * 128 * 128;
        k_copych<<<grid_of(t), 256>>>(p_x2, t, 96, 128 * 128, p_x2c, 224, 128);
    }

    // decoder level 2: 224 -> 96 @ 128
    spectral_block(p_x2c, 224, 96, 128, 8, su2_w1, su2_w2, u2_w, u2_b, tw_W1, tw_H1, p_x2o);

    // x1c = concat(up(x2o), x1) -> [4,160,256,256]
    {
        int t = BSZ * 96 * 256 * 256;
        k_up<<<grid_of(t), 256>>>(p_x2o, t, 96, 128, 128, p_x1c, 160, 0);
        t = BSZ * 64 * 256 * 256;
        k_copych<<<grid_of(t), 256>>>(p_x1, t, 64, 256 * 256, p_x1c, 160, 96);
    }

    // decoder level 1: 160 -> 64 @ 256
    spectral_block(p_x1c, 160, 64, 256, 12, su1_w1, su1_w2, u1_w, u1_b, tw_W0, tw_H0, p_x1o);

    // head: fc1 + gelu + fc2 fused
    k_head<<<BSZ * 1024, 256>>>(p_x1o, fc1_w, fc1_b, fc2_w, fc2_b, (float*)d_out);
}